// round 16
// baseline (speedup 1.0000x reference)
#include <cuda_runtime.h>
#include <cuda_fp16.h>
#include <cstdint>

// Problem constants
#define BATCH 2
#define SLEN 2048
#define DMODEL 1024
#define HEADS 16
#define HD 64
#define MDIM (BATCH * SLEN)   // 4096
#define D3 (3 * DMODEL)       // 3072

// ---------------------------------------------------------------------------
// Scratch (device globals; no allocations allowed)
// ---------------------------------------------------------------------------
__device__ __half g_xh[(size_t)MDIM * DMODEL];
__device__ __half g_w1h[(size_t)D3 * DMODEL];      // w_qkv^T [3D, D]
__device__ __half g_w2h[(size_t)DMODEL * DMODEL];  // w_out^T [D, D]
__device__ __half g_qkvh[(size_t)MDIM * D3];       // GEMM1 fp16 output
__device__ __half g_ah[(size_t)MDIM * DMODEL];     // attention fp16 output

// ---------------------------------------------------------------------------
// PTX helpers (sm_80+ only — harness targets base sm_100)
// ---------------------------------------------------------------------------
__device__ __forceinline__ uint32_t smem_u32(const void* p) {
    uint32_t a;
    asm("{ .reg .u64 t; cvta.to.shared.u64 t, %1; cvt.u32.u64 %0, t; }" : "=r"(a) : "l"(p));
    return a;
}
__device__ __forceinline__ void cp16(uint32_t dst, const void* src) {
    asm volatile("cp.async.cg.shared.global [%0], [%1], 16;" :: "r"(dst), "l"(src) : "memory");
}
#define CP_COMMIT() asm volatile("cp.async.commit_group;" ::: "memory")
#define CP_WAIT(n)  asm volatile("cp.async.wait_group %0;" :: "n"(n) : "memory")

#define LDM4(r, addr) \
    asm volatile("ldmatrix.sync.aligned.m8n8.x4.shared.b16 {%0,%1,%2,%3}, [%4];" \
        : "=r"((r)[0]), "=r"((r)[1]), "=r"((r)[2]), "=r"((r)[3]) : "r"(addr))
#define LDM4T(r, addr) \
    asm volatile("ldmatrix.sync.aligned.m8n8.x4.trans.shared.b16 {%0,%1,%2,%3}, [%4];" \
        : "=r"((r)[0]), "=r"((r)[1]), "=r"((r)[2]), "=r"((r)[3]) : "r"(addr))

#define MMA(d, a, b0, b1) \
    asm volatile("mma.sync.aligned.m16n8k16.row.col.f32.f16.f16.f32 " \
        "{%0,%1,%2,%3}, {%4,%5,%6,%7}, {%8,%9}, {%0,%1,%2,%3};" \
        : "+f"((d)[0]), "+f"((d)[1]), "+f"((d)[2]), "+f"((d)[3]) \
        : "r"((a)[0]), "r"((a)[1]), "r"((a)[2]), "r"((a)[3]), "r"(b0), "r"(b1))

__device__ __forceinline__ uint32_t packh(float a, float b) {
    __half2 t = __floats2half2_rn(a, b);
    return *reinterpret_cast<uint32_t*>(&t);
}

// exp2 via MUFU.EX2 — single-issue-slot exp on the (otherwise idle) MUFU pipe.
__device__ __forceinline__ float exp2_mufu(float x) {
    float r;
    asm("ex2.approx.f32 %0, %1;" : "=f"(r) : "f"(x));
    return r;
}

// SW64 swizzle for 64 B rows: 16 B chunk c (0..3) at row r -> c ^ ((r>>1)&3).
// 16B-aligned, ldmatrix conflict-free (even/odd rows split 64B halves, 4
// distinct chunks each).
__device__ __forceinline__ uint32_t sw64(int row, int c) {
    return (uint32_t)(row * 64 + ((c ^ ((row >> 1) & 3)) << 4));
}

#define CEXP 0.1803368801111204f   // 0.125 * log2(e)

// ---------------------------------------------------------------------------
// Cast fp32 -> fp16 elementwise (vectorized by 4)
// ---------------------------------------------------------------------------
__global__ __launch_bounds__(256) void cast_h(
    const float* __restrict__ src, __half* __restrict__ dst, int n4)
{
    int i = blockIdx.x * blockDim.x + threadIdx.x;
    if (i >= n4) return;
    float4 v = reinterpret_cast<const float4*>(src)[i];
    uint2 hp;
    hp.x = packh(v.x, v.y);
    hp.y = packh(v.z, v.w);
    reinterpret_cast<uint2*>(dst)[i] = hp;
}

// ---------------------------------------------------------------------------
// Transpose to fp16: src [R, C] fp32 -> hT [C, R] fp16
// ---------------------------------------------------------------------------
__global__ __launch_bounds__(256) void transpose_h(
    const float* __restrict__ src, __half* __restrict__ hT, int R, int C)
{
    __shared__ float t[32][33];
    const int c0 = blockIdx.x * 32, r0 = blockIdx.y * 32;
    const int tx = threadIdx.x, ty = threadIdx.y;   // 32 x 8
    #pragma unroll
    for (int j = 0; j < 4; j++)
        t[ty + 8 * j][tx] = src[(size_t)(r0 + ty + 8 * j) * C + c0 + tx];
    __syncthreads();
    #pragma unroll
    for (int j = 0; j < 4; j++)
        hT[(size_t)(c0 + ty + 8 * j) * R + r0 + tx] = __float2half_rn(t[tx][ty + 8 * j]);
}

// ---------------------------------------------------------------------------
// Warp-MMA fp16 GEMM. C[M,N] = A[M,K] @ BT[N,K]^T, fp32 accumulate.
// CTA tile 128x128, 256 threads (8 warps, 2Mx4N), warp tile 64x32.
// K chunks of 32, 4-stage cp.async pipeline, ONE __syncthreads per chunk.
// Stage = 2 x (128 rows x 64 B, SW64 swizzled) = 16 KB; 4 stages = 64 KB
// -> 3 CTAs/SM. HALF_OUT=1: fp16 out; else fp32.
// ---------------------------------------------------------------------------
#define A_MAT 8192             // 128 rows * 64 B
#define STAGE_BYTES 16384      // A + B
#define GSMEM_BYTES 65536      // 4 stages

template<int HALF_OUT>
__global__ __launch_bounds__(256, 3) void gemm_h(
    const __half* __restrict__ A, const __half* __restrict__ BT,
    float* __restrict__ C, __half* __restrict__ Ch,
    int M, int N, int K)
{
    extern __shared__ char smem[];
    const uint32_t sb = smem_u32(smem);
    const int tid = threadIdx.x;
    const int wid = tid >> 5, lane = tid & 31;
    const int m0 = blockIdx.y << 7, n0 = blockIdx.x << 7;
    const int wm = (wid >> 2) * 64, wn = (wid & 3) * 32;
    const int nc = K >> 5;      // chunks of 32

    const __half* gA = A + (size_t)m0 * K;
    const __half* gB = BT + (size_t)n0 * K;

    float acc[4][4][4];
    #pragma unroll
    for (int a = 0; a < 4; a++)
        #pragma unroll
        for (int b = 0; b < 4; b++)
            #pragma unroll
            for (int c = 0; c < 4; c++) acc[a][b][c] = 0.f;

    const int rA = lane & 15, hA = lane >> 4;
    const int qB = lane >> 3, r8 = lane & 7;
    const int bRow = (qB >> 1) * 8 + r8, bHalf = qB & 1;

    // Per-stage: A 128 rows x 4 chunks16 + B same = 1024 cp16 across 256 thr.
    auto load_stage = [&](int st, int kk) {
        uint32_t base = sb + (uint32_t)st * STAGE_BYTES;
        #pragma unroll
        for (int j = 0; j < 2; j++) {     // A: 512 chunks
            int idx = tid + j * 256;
            int row = idx >> 2, c = idx & 3;
            cp16(base + sw64(row, c), gA + kk + (size_t)row * K + c * 8);
        }
        #pragma unroll
        for (int j = 0; j < 2; j++) {     // B: 512 chunks
            int idx = tid + j * 256;
            int row = idx >> 2, c = idx & 3;
            cp16(base + A_MAT + sw64(row, c), gB + kk + (size_t)row * K + c * 8);
        }
        CP_COMMIT();
    };

    auto compute_stage = [&](int st) {
        uint32_t base = sb + (uint32_t)st * STAGE_BYTES;
        const uint32_t sA = base, sB = base + A_MAT;
        #pragma unroll
        for (int ks = 0; ks < 2; ks++) {
            uint32_t aF[4][4], bF[2][4];
            #pragma unroll
            for (int mt = 0; mt < 4; mt++) {
                int row = wm + mt * 16 + rA;
                LDM4(aF[mt], sA + sw64(row, ks * 2 + hA));
            }
            #pragma unroll
            for (int bt = 0; bt < 2; bt++) {
                int row = wn + bt * 16 + bRow;
                LDM4(bF[bt], sB + sw64(row, ks * 2 + bHalf));
            }
            #pragma unroll
            for (int mt = 0; mt < 4; mt++)
                #pragma unroll
                for (int nt = 0; nt < 4; nt++) {
                    const int bt = nt >> 1, p = (nt & 1) * 2;
                    MMA(acc[mt][nt], aF[mt], bF[bt][p], bF[bt][p + 1]);
                }
        }
    };

    // 4-stage pipeline, one barrier per chunk, prefetch distance 3.
    load_stage(0, 0);
    load_stage(1, 32);
    load_stage(2, 64);
    int sc = 0;                 // compute stage index (mod 4)
    for (int ic = 0; ic < nc; ic++) {
        if (ic + 3 < nc)      { CP_WAIT(3); }
        else if (ic + 2 < nc) { CP_WAIT(2); }
        else if (ic + 1 < nc) { CP_WAIT(1); }
        else                  { CP_WAIT(0); }
        __syncthreads();        // stage sc ready; stage (sc+3)%4 fully consumed
        if (ic + 3 < nc) {
            load_stage((sc + 3) & 3, (ic + 3) << 5);
        }
        compute_stage(sc);
        sc = (sc + 1) & 3;
    }

    const int rowb = lane >> 2, colb = (lane & 3) * 2;
    #pragma unroll
    for (int mt = 0; mt < 4; mt++)
        #pragma unroll
        for (int nt = 0; nt < 4; nt++) {
            const int r = m0 + wm + mt * 16 + rowb;
            const int cI = n0 + wn + nt * 8 + colb;
            float v0 = acc[mt][nt][0], v1 = acc[mt][nt][1];
            float v2 = acc[mt][nt][2], v3 = acc[mt][nt][3];
            if (HALF_OUT) {
                *(uint32_t*)&Ch[(size_t)r * N + cI]       = packh(v0, v1);
                *(uint32_t*)&Ch[(size_t)(r + 8) * N + cI] = packh(v2, v3);
            } else {
                *(float2*)&C[(size_t)r * N + cI]       = make_float2(v0, v1);
                *(float2*)&C[(size_t)(r + 8) * N + cI] = make_float2(v2, v3);
            }
        }
}

// ---------------------------------------------------------------------------
// Tensor-core causal flash attention, pure fp16 operands, fp32 accum/softmax.
// exp via MUFU. Q frags hoisted. CTA: 256 threads (8 warps), q-tile 128,
// k-tile 64, 3-stage cp.async KV pipeline, ONE __syncthreads per iteration.
// 73.7 KB smem -> 3 CTAs/SM. (Unchanged from the 247.9 us config.)
// ---------------------------------------------------------------------------
#define FQ_BYTES 18432          // 128*144
#define FKV_MAT 9216            // 64*144
#define FSTAGE (2 * FKV_MAT)    // 18432 (K + V)
#define FSMEM (FQ_BYTES + 3 * FSTAGE)   // 73728

__global__ __launch_bounds__(256) void flash_mma(
    const __half* __restrict__ qkv, __half* __restrict__ outh)
{
    extern __shared__ char smem[];
    const uint32_t sb = smem_u32(smem);
    const uint32_t sQ = sb;
    const uint32_t sStage = sb + FQ_BYTES;

    const int tid = threadIdx.x, wid = tid >> 5, lane = tid & 31;
    const int q0 = ((int)gridDim.x - 1 - (int)blockIdx.x) * 128;
    const int h = blockIdx.y, b = blockIdx.z;
    const int qrow0 = q0 + wid * 16;

    const __half* baseP = qkv + (size_t)b * SLEN * D3 + h * HD;

    const int rA = lane & 15, hA = lane >> 4;              // A frag (Q rows)
    const int qB = lane >> 3, r8 = lane & 7;               // B frag (K rows)
    const int bRow = (qB >> 1) * 8 + r8, bHalf = qB & 1;
    const int grp = lane >> 3, l8 = lane & 7;              // V trans frag

    // Stage Q tile: 1024 chunks (committed as part of KV group 0)
    {
        #pragma unroll
        for (int j = 0; j < 4; j++) {
            int idx = tid + j * 256;
            int row = idx >> 3, c = idx & 7;
            cp16(sQ + (uint32_t)(row * 144 + c * 16),
                 baseP + (size_t)(q0 + row) * D3 + c * 8);
        }
    }

    const int nk = q0 / 64 + 2;   // always >= 2

    auto load_kv = [&](int st, int k0) {
        uint32_t base = sStage + (uint32_t)st * FSTAGE;
        #pragma unroll
        for (int j = 0; j < 4; j++) {   // K + V: 1024 chunks
            int idx = tid + j * 256;
            int mat = idx >> 9, row = (idx >> 3) & 63, c = idx & 7;
            int seg = mat ? 2 * DMODEL : DMODEL;   // 0=K, 1=V
            cp16(base + (uint32_t)mat * FKV_MAT + (uint32_t)(row * 144 + c * 16),
                 baseP + (size_t)(k0 + row) * D3 + seg + c * 8);
        }
        CP_COMMIT();
    };

    float oacc[8][4];
    #pragma unroll
    for (int i = 0; i < 8; i++)
        #pragma unroll
        for (int j = 0; j < 4; j++) oacc[i][j] = 0.f;
    float m0 = -1e30f, m1 = -1e30f, l0 = 0.f, l1 = 0.f;

    uint32_t qF[4][4];   // hoisted Q fragments (per ks)

    load_kv(0, 0);     // group0 = Q + KV0
    load_kv(1, 64);    // group1 = KV1

    int sc = 0;        // compute stage (mod 3)
    for (int it = 0; it < nk; it++) {
        const int k0 = it * 64;
        if (it + 1 < nk) { CP_WAIT(1); } else { CP_WAIT(0); }
        __syncthreads();   // stage sc ready for all; stage (it-1)%3 free for reuse

        if (it == 0) {     // Q resident now (group0); hoist frags once
            #pragma unroll
            for (int ks = 0; ks < 4; ks++) {
                uint32_t aoff = (uint32_t)((wid * 16 + rA) * 144 + ks * 32 + hA * 16);
                LDM4(qF[ks], sQ + aoff);
            }
        }

        if (it + 2 < nk) {
            int sld = sc + 2 >= 3 ? sc - 1 : sc + 2;
            load_kv(sld, (it + 2) * 64);
        }

        if (k0 <= qrow0 + 15) {
            const uint32_t st = sStage + (uint32_t)sc * FSTAGE;
            const uint32_t sK = st, sV = st + FKV_MAT;

            // ---- S = Q K^T, 16x64 per warp
            float sfrag[8][4];
            #pragma unroll
            for (int i = 0; i < 8; i++)
                #pragma unroll
                for (int j = 0; j < 4; j++) sfrag[i][j] = 0.f;

            #pragma unroll
            for (int ks = 0; ks < 4; ks++) {
                uint32_t kF[4][4];
                #pragma unroll
                for (int bt = 0; bt < 4; bt++) {
                    uint32_t off = (uint32_t)((bt * 16 + bRow) * 144 + ks * 32 + bHalf * 16);
                    LDM4(kF[bt], sK + off);
                }
                #pragma unroll
                for (int nt = 0; nt < 8; nt++) {
                    const int bt = nt >> 1, p = (nt & 1) * 2;
                    MMA(sfrag[nt], qF[ks], kF[bt][p], kF[bt][p + 1]);
                }
            }

            // ---- causal mask on diagonal tiles
            const int row0 = qrow0 + (lane >> 2), row1 = row0 + 8;
            if (k0 + 63 > qrow0) {
                #pragma unroll
                for (int nt = 0; nt < 8; nt++) {
                    int col = k0 + nt * 8 + ((lane & 3) << 1);
                    if (col > row0)     sfrag[nt][0] = -1e30f;
                    if (col + 1 > row0) sfrag[nt][1] = -1e30f;
                    if (col > row1)     sfrag[nt][2] = -1e30f;
                    if (col + 1 > row1) sfrag[nt][3] = -1e30f;
                }
            }

            // ---- online softmax (exp on MUFU pipe)
            float mc0 = -1e30f, mc1 = -1e30f;
            #pragma unroll
            for (int nt = 0; nt < 8; nt++) {
                mc0 = fmaxf(mc0, fmaxf(sfrag[nt][0], sfrag[nt][1]));
                mc1 = fmaxf(mc1, fmaxf(sfrag[nt][2], sfrag[nt][3]));
            }
            mc0 = fmaxf(mc0, __shfl_xor_sync(0xffffffffu, mc0, 1));
            mc0 = fmaxf(mc0, __shfl_xor_sync(0xffffffffu, mc0, 2));
            mc1 = fmaxf(mc1, __shfl_xor_sync(0xffffffffu, mc1, 1));
            mc1 = fmaxf(mc1, __shfl_xor_sync(0xffffffffu, mc1, 2));
            const float mn0 = fmaxf(m0, mc0), mn1 = fmaxf(m1, mc1);
            const float corr0 = exp2_mufu((m0 - mn0) * CEXP);
            const float corr1 = exp2_mufu((m1 - mn1) * CEXP);
            m0 = mn0; m1 = mn1;

            float rs0 = 0.f, rs1 = 0.f;
            #pragma unroll
            for (int nt = 0; nt < 8; nt++) {
                sfrag[nt][0] = exp2_mufu((sfrag[nt][0] - mn0) * CEXP);
                sfrag[nt][1] = exp2_mufu((sfrag[nt][1] - mn0) * CEXP);
                sfrag[nt][2] = exp2_mufu((sfrag[nt][2] - mn1) * CEXP);
                sfrag[nt][3] = exp2_mufu((sfrag[nt][3] - mn1) * CEXP);
                rs0 += sfrag[nt][0] + sfrag[nt][1];
                rs1 += sfrag[nt][2] + sfrag[nt][3];
            }
            rs0 += __shfl_xor_sync(0xffffffffu, rs0, 1);
            rs0 += __shfl_xor_sync(0xffffffffu, rs0, 2);
            rs1 += __shfl_xor_sync(0xffffffffu, rs1, 1);
            rs1 += __shfl_xor_sync(0xffffffffu, rs1, 2);
            l0 = l0 * corr0 + rs0;
            l1 = l1 * corr1 + rs1;
            #pragma unroll
            for (int nt = 0; nt < 8; nt++) {
                oacc[nt][0] *= corr0; oacc[nt][1] *= corr0;
                oacc[nt][2] *= corr1; oacc[nt][3] *= corr1;
            }

            // ---- O += P V (single fp16 P and V)
            #pragma unroll
            for (int t = 0; t < 4; t++) {
                uint32_t pF[4];
                pF[0] = packh(sfrag[2 * t][0], sfrag[2 * t][1]);
                pF[1] = packh(sfrag[2 * t][2], sfrag[2 * t][3]);
                pF[2] = packh(sfrag[2 * t + 1][0], sfrag[2 * t + 1][1]);
                pF[3] = packh(sfrag[2 * t + 1][2], sfrag[2 * t + 1][3]);
                #pragma unroll
                for (int np = 0; np < 4; np++) {
                    uint32_t vF[4];
                    uint32_t off = (uint32_t)((t * 16 + (grp & 1) * 8 + l8) * 144 +
                                              (np * 16 + (grp >> 1) * 8) * 2);
                    LDM4T(vF, sV + off);
                    MMA(oacc[np * 2],     pF, vF[0], vF[1]);
                    MMA(oacc[np * 2 + 1], pF, vF[2], vF[3]);
                }
            }
        }
        sc = (sc + 1 == 3) ? 0 : sc + 1;
    }

    // ---- finalize: O /= l, write fp16 output [B*S, D]
    const float inv0 = 1.f / l0, inv1 = 1.f / l1;
    const int row0 = q0 + wid * 16 + (lane >> 2);
    const int colb = h * HD + (lane & 3) * 2;
    #pragma unroll
    for (int nt = 0; nt < 8; nt++) {
        float v0 = oacc[nt][0] * inv0, v1 = oacc[nt][1] * inv0;
        float v2 = oacc[nt][2] * inv1, v3 = oacc[nt][3] * inv1;
        size_t o0 = (size_t)(b * SLEN + row0) * DMODEL + colb + nt * 8;
        size_t o1 = (size_t)(b * SLEN + row0 + 8) * DMODEL + colb + nt * 8;
        *(uint32_t*)&outh[o0] = packh(v0, v1);
        *(uint32_t*)&outh[o1] = packh(v2, v3);
    }
}

// ---------------------------------------------------------------------------
// kernel_launch
// ---------------------------------------------------------------------------
extern "C" void kernel_launch(void* const* d_in, const int* in_sizes, int n_in,
                              void* d_out, int out_size)
{
    const float* x     = (const float*)d_in[0];
    const float* w_qkv = (const float*)d_in[1];
    const float* w_out = (const float*)d_in[2];
    float* out = (float*)d_out;

    __half *xh, *w1h, *w2h, *qh, *ah;
    cudaGetSymbolAddress((void**)&xh, g_xh);
    cudaGetSymbolAddress((void**)&w1h, g_w1h);
    cudaGetSymbolAddress((void**)&w2h, g_w2h);
    cudaGetSymbolAddress((void**)&qh, g_qkvh);
    cudaGetSymbolAddress((void**)&ah, g_ah);

    cudaFuncSetAttribute(gemm_h<0>, cudaFuncAttributeMaxDynamicSharedMemorySize, GSMEM_BYTES);
    cudaFuncSetAttribute(gemm_h<1>, cudaFuncAttributeMaxDynamicSharedMemorySize, GSMEM_BYTES);
    cudaFuncSetAttribute(flash_mma, cudaFuncAttributeMaxDynamicSharedMemorySize, FSMEM);

    const int M = MDIM;

    cast_h<<<(M * DMODEL / 4 + 255) / 256, 256>>>(x, xh, M * DMODEL / 4);
    transpose_h<<<dim3(D3 / 32, DMODEL / 32), dim3(32, 8)>>>(w_qkv, w1h, DMODEL, D3);
    transpose_h<<<dim3(DMODEL / 32, DMODEL / 32), dim3(32, 8)>>>(w_out, w2h, DMODEL, DMODEL);

    // 1) qkv (fp16) = x @ w_qkv
    gemm_h<1><<<dim3(D3 / 128, M / 128), 256, GSMEM_BYTES>>>(
        xh, w1h, nullptr, qh, M, D3, DMODEL);

    // 2) tensor-core causal flash attention -> fp16 att
    flash_mma<<<dim3(SLEN / 128, HEADS, BATCH), 256, FSMEM>>>(qh, ah);

    // 3) out = att @ w_out (fp32 out)
    gemm_h<0><<<dim3(DMODEL / 128, M / 128), 256, GSMEM_BYTES>>>(
        ah, w2h, out, nullptr, M, DMODEL, DMODEL);
}

// round 17
// speedup vs baseline: 1.1870x; 1.1870x over previous
#include <cuda_runtime.h>
#include <cuda_fp16.h>
#include <cstdint>

// Problem constants
#define BATCH 2
#define SLEN 2048
#define DMODEL 1024
#define HEADS 16
#define HD 64
#define MDIM (BATCH * SLEN)   // 4096
#define D3 (3 * DMODEL)       // 3072

#define CEXP 0.1803368801111204f   // 0.125 * log2(e), folded into Q at GEMM1

// ---------------------------------------------------------------------------
// Scratch (device globals; no allocations allowed)
// ---------------------------------------------------------------------------
__device__ __half g_xh[(size_t)MDIM * DMODEL];
__device__ __half g_w1h[(size_t)D3 * DMODEL];      // w_qkv^T [3D, D]
__device__ __half g_w2h[(size_t)DMODEL * DMODEL];  // w_out^T [D, D]
__device__ __half g_qkvh[(size_t)MDIM * D3];       // GEMM1 fp16 output (Q pre-scaled)
__device__ __half g_ah[(size_t)MDIM * DMODEL];     // attention fp16 output

// ---------------------------------------------------------------------------
// PTX helpers (sm_80+ only — harness targets base sm_100)
// ---------------------------------------------------------------------------
__device__ __forceinline__ uint32_t smem_u32(const void* p) {
    uint32_t a;
    asm("{ .reg .u64 t; cvta.to.shared.u64 t, %1; cvt.u32.u64 %0, t; }" : "=r"(a) : "l"(p));
    return a;
}
__device__ __forceinline__ void cp16(uint32_t dst, const void* src) {
    asm volatile("cp.async.cg.shared.global [%0], [%1], 16;" :: "r"(dst), "l"(src) : "memory");
}
#define CP_COMMIT() asm volatile("cp.async.commit_group;" ::: "memory")
#define CP_WAIT(n)  asm volatile("cp.async.wait_group %0;" :: "n"(n) : "memory")

#define LDM4(r, addr) \
    asm volatile("ldmatrix.sync.aligned.m8n8.x4.shared.b16 {%0,%1,%2,%3}, [%4];" \
        : "=r"((r)[0]), "=r"((r)[1]), "=r"((r)[2]), "=r"((r)[3]) : "r"(addr))
#define LDM4T(r, addr) \
    asm volatile("ldmatrix.sync.aligned.m8n8.x4.trans.shared.b16 {%0,%1,%2,%3}, [%4];" \
        : "=r"((r)[0]), "=r"((r)[1]), "=r"((r)[2]), "=r"((r)[3]) : "r"(addr))

#define MMA(d, a, b0, b1) \
    asm volatile("mma.sync.aligned.m16n8k16.row.col.f32.f16.f16.f32 " \
        "{%0,%1,%2,%3}, {%4,%5,%6,%7}, {%8,%9}, {%0,%1,%2,%3};" \
        : "+f"((d)[0]), "+f"((d)[1]), "+f"((d)[2]), "+f"((d)[3]) \
        : "r"((a)[0]), "r"((a)[1]), "r"((a)[2]), "r"((a)[3]), "r"(b0), "r"(b1))

__device__ __forceinline__ uint32_t packh(float a, float b) {
    __half2 t = __floats2half2_rn(a, b);
    return *reinterpret_cast<uint32_t*>(&t);
}

// exp2 via MUFU.EX2 — single-issue-slot exp on the (otherwise idle) MUFU pipe.
__device__ __forceinline__ float exp2_mufu(float x) {
    float r;
    asm("ex2.approx.f32 %0, %1;" : "=f"(r) : "f"(x));
    return r;
}

// ---------------------------------------------------------------------------
// Fused prep: grid-partitioned cast (x->fp16) + transpose w_qkv + transpose
// w_out. Block = (32,8). Saves two kernel-launch overheads.
//   blocks [0, NCAST)                : cast x (each block: 256 float4)
//   blocks [NCAST, NCAST+NT1)        : transpose w_qkv tile
//   blocks [NCAST+NT1, NCAST+NT1+NT2): transpose w_out tile
// ---------------------------------------------------------------------------
#define NCAST (MDIM * DMODEL / 4 / 256)       // 4096
#define NT1   ((D3 / 32) * (DMODEL / 32))     // 3072
#define NT2   ((DMODEL / 32) * (DMODEL / 32)) // 1024

__global__ __launch_bounds__(256) void prep_fused(
    const float* __restrict__ x, __half* __restrict__ xh,
    const float* __restrict__ w1, __half* __restrict__ w1T,
    const float* __restrict__ w2, __half* __restrict__ w2T)
{
    const int bid = blockIdx.x;
    const int tx = threadIdx.x, ty = threadIdx.y;
    const int tid = ty * 32 + tx;

    if (bid < NCAST) {
        int i = bid * 256 + tid;
        float4 v = reinterpret_cast<const float4*>(x)[i];
        uint2 hp;
        hp.x = packh(v.x, v.y);
        hp.y = packh(v.z, v.w);
        reinterpret_cast<uint2*>(xh)[i] = hp;
        return;
    }

    __shared__ float t[32][33];
    const float* src;
    __half* dstT;
    int R, C, bx, by;
    if (bid < NCAST + NT1) {
        int id = bid - NCAST;
        src = w1; dstT = w1T; R = DMODEL; C = D3;
        bx = id % (D3 / 32); by = id / (D3 / 32);
    } else {
        int id = bid - NCAST - NT1;
        src = w2; dstT = w2T; R = DMODEL; C = DMODEL;
        bx = id % (DMODEL / 32); by = id / (DMODEL / 32);
    }
    const int c0 = bx * 32, r0 = by * 32;
    #pragma unroll
    for (int j = 0; j < 4; j++)
        t[ty + 8 * j][tx] = src[(size_t)(r0 + ty + 8 * j) * C + c0 + tx];
    __syncthreads();
    #pragma unroll
    for (int j = 0; j < 4; j++)
        dstT[(size_t)(c0 + ty + 8 * j) * R + r0 + tx] = __float2half_rn(t[tx][ty + 8 * j]);
}

// ---------------------------------------------------------------------------
// Warp-MMA fp16 GEMM (R14 config). C[M,N] = A[M,K] @ BT[N,K]^T, fp32 accum.
// CTA tile 128x128, 256 threads (8 warps, 2Mx4N), warp tile 64x32.
// K chunks of 64, 3-stage cp.async pipeline, ONE __syncthreads per chunk.
// 110.6 KB smem -> 2 CTAs/SM.
// HALF_OUT=1: fp16 out; columns cI < scale_end are multiplied by CEXP
// (folds the attention softmax scale into the Q segment).
// ---------------------------------------------------------------------------
#define A_MAT 18432            // 128 rows * 144 B
#define STAGE_BYTES 36864      // A + B
#define GSMEM_BYTES 110592     // 3 stages

template<int HALF_OUT>
__global__ __launch_bounds__(256, 2) void gemm_h(
    const __half* __restrict__ A, const __half* __restrict__ BT,
    float* __restrict__ C, __half* __restrict__ Ch,
    int M, int N, int K, int scale_end)
{
    extern __shared__ char smem[];
    const uint32_t sb = smem_u32(smem);
    const int tid = threadIdx.x;
    const int wid = tid >> 5, lane = tid & 31;
    const int m0 = blockIdx.y << 7, n0 = blockIdx.x << 7;
    const int wm = (wid >> 2) * 64, wn = (wid & 3) * 32;
    const int nc = K >> 6;

    const __half* gA = A + (size_t)m0 * K;
    const __half* gB = BT + (size_t)n0 * K;

    float acc[4][4][4];
    #pragma unroll
    for (int a = 0; a < 4; a++)
        #pragma unroll
        for (int b = 0; b < 4; b++)
            #pragma unroll
            for (int c = 0; c < 4; c++) acc[a][b][c] = 0.f;

    const int rA = lane & 15, hA = lane >> 4;
    const int qB = lane >> 3, r8 = lane & 7;
    const int bRow = (qB >> 1) * 8 + r8, bHalf = qB & 1;

    auto load_stage = [&](int st, int kk) {
        uint32_t base = sb + (uint32_t)st * STAGE_BYTES;
        #pragma unroll
        for (int j = 0; j < 4; j++) {     // A: 1024 chunks
            int idx = tid + j * 256;
            int row = idx >> 3, c = idx & 7;
            cp16(base + (uint32_t)(row * 144 + c * 16), gA + kk + (size_t)row * K + c * 8);
        }
        #pragma unroll
        for (int j = 0; j < 4; j++) {     // B: 1024 chunks
            int idx = tid + j * 256;
            int row = idx >> 3, c = idx & 7;
            cp16(base + A_MAT + (uint32_t)(row * 144 + c * 16), gB + kk + (size_t)row * K + c * 8);
        }
        CP_COMMIT();
    };

    auto compute_stage = [&](int st) {
        uint32_t base = sb + (uint32_t)st * STAGE_BYTES;
        const uint32_t sA = base, sB = base + A_MAT;
        #pragma unroll
        for (int ks = 0; ks < 4; ks++) {
            uint32_t aF[4][4], bF[2][4];
            #pragma unroll
            for (int mt = 0; mt < 4; mt++) {
                uint32_t off = (uint32_t)((wm + mt * 16 + rA) * 144 + ks * 32 + hA * 16);
                LDM4(aF[mt], sA + off);
            }
            #pragma unroll
            for (int bt = 0; bt < 2; bt++) {
                uint32_t off = (uint32_t)((wn + bt * 16 + bRow) * 144 + ks * 32 + bHalf * 16);
                LDM4(bF[bt], sB + off);
            }
            #pragma unroll
            for (int mt = 0; mt < 4; mt++)
                #pragma unroll
                for (int nt = 0; nt < 4; nt++) {
                    const int bt = nt >> 1, p = (nt & 1) * 2;
                    MMA(acc[mt][nt], aF[mt], bF[bt][p], bF[bt][p + 1]);
                }
        }
    };

    // 3-stage pipeline, one barrier per chunk.
    load_stage(0, 0);
    load_stage(1, 64);
    int sc = 0;
    for (int ic = 0; ic < nc; ic++) {
        if (ic + 1 < nc) { CP_WAIT(1); } else { CP_WAIT(0); }
        __syncthreads();
        if (ic + 2 < nc) {
            int sld = sc + 2 >= 3 ? sc - 1 : sc + 2;
            load_stage(sld, (ic + 2) << 6);
        }
        compute_stage(sc);
        sc = (sc + 1 == 3) ? 0 : sc + 1;
    }

    const int rowb = lane >> 2, colb = (lane & 3) * 2;
    #pragma unroll
    for (int mt = 0; mt < 4; mt++)
        #pragma unroll
        for (int nt = 0; nt < 4; nt++) {
            const int r = m0 + wm + mt * 16 + rowb;
            const int cI = n0 + wn + nt * 8 + colb;
            float v0 = acc[mt][nt][0], v1 = acc[mt][nt][1];
            float v2 = acc[mt][nt][2], v3 = acc[mt][nt][3];
            if (HALF_OUT) {
                if (cI < scale_end) {   // Q columns: fold softmax scale
                    v0 *= CEXP; v1 *= CEXP; v2 *= CEXP; v3 *= CEXP;
                }
                *(uint32_t*)&Ch[(size_t)r * N + cI]       = packh(v0, v1);
                *(uint32_t*)&Ch[(size_t)(r + 8) * N + cI] = packh(v2, v3);
            } else {
                *(float2*)&C[(size_t)r * N + cI]       = make_float2(v0, v1);
                *(float2*)&C[(size_t)(r + 8) * N + cI] = make_float2(v2, v3);
            }
        }
}

// ---------------------------------------------------------------------------
// Tensor-core causal flash attention, pure fp16 operands, fp32 accum/softmax.
// Q pre-scaled by 0.125*log2e at GEMM1 -> scores already in log2 domain;
// exp via MUFU. Q frags hoisted. CTA: 256 threads (8 warps), q-tile 128,
// k-tile 64, 3-stage cp.async KV pipeline, ONE __syncthreads per iteration.
// 73.7 KB smem -> 3 CTAs/SM.
// ---------------------------------------------------------------------------
#define FQ_BYTES 18432          // 128*144
#define FKV_MAT 9216            // 64*144
#define FSTAGE (2 * FKV_MAT)    // 18432 (K + V)
#define FSMEM (FQ_BYTES + 3 * FSTAGE)   // 73728

__global__ __launch_bounds__(256) void flash_mma(
    const __half* __restrict__ qkv, __half* __restrict__ outh)
{
    extern __shared__ char smem[];
    const uint32_t sb = smem_u32(smem);
    const uint32_t sQ = sb;
    const uint32_t sStage = sb + FQ_BYTES;

    const int tid = threadIdx.x, wid = tid >> 5, lane = tid & 31;
    const int q0 = ((int)gridDim.x - 1 - (int)blockIdx.x) * 128;
    const int h = blockIdx.y, b = blockIdx.z;
    const int qrow0 = q0 + wid * 16;

    const __half* baseP = qkv + (size_t)b * SLEN * D3 + h * HD;

    const int rA = lane & 15, hA = lane >> 4;              // A frag (Q rows)
    const int qB = lane >> 3, r8 = lane & 7;               // B frag (K rows)
    const int bRow = (qB >> 1) * 8 + r8, bHalf = qB & 1;
    const int grp = lane >> 3, l8 = lane & 7;              // V trans frag

    // Stage Q tile: 1024 chunks (committed as part of KV group 0)
    {
        #pragma unroll
        for (int j = 0; j < 4; j++) {
            int idx = tid + j * 256;
            int row = idx >> 3, c = idx & 7;
            cp16(sQ + (uint32_t)(row * 144 + c * 16),
                 baseP + (size_t)(q0 + row) * D3 + c * 8);
        }
    }

    const int nk = q0 / 64 + 2;   // always >= 2

    auto load_kv = [&](int st, int k0) {
        uint32_t base = sStage + (uint32_t)st * FSTAGE;
        #pragma unroll
        for (int j = 0; j < 4; j++) {   // K + V: 1024 chunks
            int idx = tid + j * 256;
            int mat = idx >> 9, row = (idx >> 3) & 63, c = idx & 7;
            int seg = mat ? 2 * DMODEL : DMODEL;   // 0=K, 1=V
            cp16(base + (uint32_t)mat * FKV_MAT + (uint32_t)(row * 144 + c * 16),
                 baseP + (size_t)(k0 + row) * D3 + seg + c * 8);
        }
        CP_COMMIT();
    };

    float oacc[8][4];
    #pragma unroll
    for (int i = 0; i < 8; i++)
        #pragma unroll
        for (int j = 0; j < 4; j++) oacc[i][j] = 0.f;
    float m0 = -1e30f, m1 = -1e30f, l0 = 0.f, l1 = 0.f;

    uint32_t qF[4][4];   // hoisted Q fragments (per ks)

    load_kv(0, 0);     // group0 = Q + KV0
    load_kv(1, 64);    // group1 = KV1

    int sc = 0;        // compute stage (mod 3)
    for (int it = 0; it < nk; it++) {
        const int k0 = it * 64;
        if (it + 1 < nk) { CP_WAIT(1); } else { CP_WAIT(0); }
        __syncthreads();   // stage sc ready for all; stage (it-1)%3 free for reuse

        if (it == 0) {     // Q resident now (group0); hoist frags once
            #pragma unroll
            for (int ks = 0; ks < 4; ks++) {
                uint32_t aoff = (uint32_t)((wid * 16 + rA) * 144 + ks * 32 + hA * 16);
                LDM4(qF[ks], sQ + aoff);
            }
        }

        if (it + 2 < nk) {
            int sld = sc + 2 >= 3 ? sc - 1 : sc + 2;
            load_kv(sld, (it + 2) * 64);
        }

        if (k0 <= qrow0 + 15) {
            const uint32_t st = sStage + (uint32_t)sc * FSTAGE;
            const uint32_t sK = st, sV = st + FKV_MAT;

            // ---- S' = (Q*cexp) K^T  (already log2-domain), 16x64 per warp
            float sfrag[8][4];
            #pragma unroll
            for (int i = 0; i < 8; i++)
                #pragma unroll
                for (int j = 0; j < 4; j++) sfrag[i][j] = 0.f;

            #pragma unroll
            for (int ks = 0; ks < 4; ks++) {
                uint32_t kF[4][4];
                #pragma unroll
                for (int bt = 0; bt < 4; bt++) {
                    uint32_t off = (uint32_t)((bt * 16 + bRow) * 144 + ks * 32 + bHalf * 16);
                    LDM4(kF[bt], sK + off);
                }
                #pragma unroll
                for (int nt = 0; nt < 8; nt++) {
                    const int bt = nt >> 1, p = (nt & 1) * 2;
                    MMA(sfrag[nt], qF[ks], kF[bt][p], kF[bt][p + 1]);
                }
            }

            // ---- causal mask on diagonal tiles
            const int row0 = qrow0 + (lane >> 2), row1 = row0 + 8;
            if (k0 + 63 > qrow0) {
                #pragma unroll
                for (int nt = 0; nt < 8; nt++) {
                    int col = k0 + nt * 8 + ((lane & 3) << 1);
                    if (col > row0)     sfrag[nt][0] = -1e30f;
                    if (col + 1 > row0) sfrag[nt][1] = -1e30f;
                    if (col > row1)     sfrag[nt][2] = -1e30f;
                    if (col + 1 > row1) sfrag[nt][3] = -1e30f;
                }
            }

            // ---- online softmax (log2 domain, exp on MUFU pipe)
            float mc0 = -1e30f, mc1 = -1e30f;
            #pragma unroll
            for (int nt = 0; nt < 8; nt++) {
                mc0 = fmaxf(mc0, fmaxf(sfrag[nt][0], sfrag[nt][1]));
                mc1 = fmaxf(mc1, fmaxf(sfrag[nt][2], sfrag[nt][3]));
            }
            mc0 = fmaxf(mc0, __shfl_xor_sync(0xffffffffu, mc0, 1));
            mc0 = fmaxf(mc0, __shfl_xor_sync(0xffffffffu, mc0, 2));
            mc1 = fmaxf(mc1, __shfl_xor_sync(0xffffffffu, mc1, 1));
            mc1 = fmaxf(mc1, __shfl_xor_sync(0xffffffffu, mc1, 2));
            const float mn0 = fmaxf(m0, mc0), mn1 = fmaxf(m1, mc1);
            const float corr0 = exp2_mufu(m0 - mn0);
            const float corr1 = exp2_mufu(m1 - mn1);
            m0 = mn0; m1 = mn1;

            float rs0 = 0.f, rs1 = 0.f;
            #pragma unroll
            for (int nt = 0; nt < 8; nt++) {
                sfrag[nt][0] = exp2_mufu(sfrag[nt][0] - mn0);
                sfrag[nt][1] = exp2_mufu(sfrag[nt][1] - mn0);
                sfrag[nt][2] = exp2_mufu(sfrag[nt][2] - mn1);
                sfrag[nt][3] = exp2_mufu(sfrag[nt][3] - mn1);
                rs0 += sfrag[nt][0] + sfrag[nt][1];
                rs1 += sfrag[nt][2] + sfrag[nt][3];
            }
            rs0 += __shfl_xor_sync(0xffffffffu, rs0, 1);
            rs0 += __shfl_xor_sync(0xffffffffu, rs0, 2);
            rs1 += __shfl_xor_sync(0xffffffffu, rs1, 1);
            rs1 += __shfl_xor_sync(0xffffffffu, rs1, 2);
            l0 = l0 * corr0 + rs0;
            l1 = l1 * corr1 + rs1;
            #pragma unroll
            for (int nt = 0; nt < 8; nt++) {
                oacc[nt][0] *= corr0; oacc[nt][1] *= corr0;
                oacc[nt][2] *= corr1; oacc[nt][3] *= corr1;
            }

            // ---- O += P V (single fp16 P and V)
            #pragma unroll
            for (int t = 0; t < 4; t++) {
                uint32_t pF[4];
                pF[0] = packh(sfrag[2 * t][0], sfrag[2 * t][1]);
                pF[1] = packh(sfrag[2 * t][2], sfrag[2 * t][3]);
                pF[2] = packh(sfrag[2 * t + 1][0], sfrag[2 * t + 1][1]);
                pF[3] = packh(sfrag[2 * t + 1][2], sfrag[2 * t + 1][3]);
                #pragma unroll
                for (int np = 0; np < 4; np++) {
                    uint32_t vF[4];
                    uint32_t off = (uint32_t)((t * 16 + (grp & 1) * 8 + l8) * 144 +
                                              (np * 16 + (grp >> 1) * 8) * 2);
                    LDM4T(vF, sV + off);
                    MMA(oacc[np * 2],     pF, vF[0], vF[1]);
                    MMA(oacc[np * 2 + 1], pF, vF[2], vF[3]);
                }
            }
        }
        sc = (sc + 1 == 3) ? 0 : sc + 1;
    }

    // ---- finalize: O /= l, write fp16 output [B*S, D]
    const float inv0 = 1.f / l0, inv1 = 1.f / l1;
    const int row0 = q0 + wid * 16 + (lane >> 2);
    const int colb = h * HD + (lane & 3) * 2;
    #pragma unroll
    for (int nt = 0; nt < 8; nt++) {
        float v0 = oacc[nt][0] * inv0, v1 = oacc[nt][1] * inv0;
        float v2 = oacc[nt][2] * inv1, v3 = oacc[nt][3] * inv1;
        size_t o0 = (size_t)(b * SLEN + row0) * DMODEL + colb + nt * 8;
        size_t o1 = (size_t)(b * SLEN + row0 + 8) * DMODEL + colb + nt * 8;
        *(uint32_t*)&outh[o0] = packh(v0, v1);
        *(uint32_t*)&outh[o1] = packh(v2, v3);
    }
}

// ---------------------------------------------------------------------------
// kernel_launch
// ---------------------------------------------------------------------------
extern "C" void kernel_launch(void* const* d_in, const int* in_sizes, int n_in,
                              void* d_out, int out_size)
{
    const float* x     = (const float*)d_in[0];
    const float* w_qkv = (const float*)d_in[1];
    const float* w_out = (const float*)d_in[2];
    float* out = (float*)d_out;

    __half *xh, *w1h, *w2h, *qh, *ah;
    cudaGetSymbolAddress((void**)&xh, g_xh);
    cudaGetSymbolAddress((void**)&w1h, g_w1h);
    cudaGetSymbolAddress((void**)&w2h, g_w2h);
    cudaGetSymbolAddress((void**)&qh, g_qkvh);
    cudaGetSymbolAddress((void**)&ah, g_ah);

    cudaFuncSetAttribute(gemm_h<0>, cudaFuncAttributeMaxDynamicSharedMemorySize, GSMEM_BYTES);
    cudaFuncSetAttribute(gemm_h<1>, cudaFuncAttributeMaxDynamicSharedMemorySize, GSMEM_BYTES);
    cudaFuncSetAttribute(flash_mma, cudaFuncAttributeMaxDynamicSharedMemorySize, FSMEM);

    const int M = MDIM;

    // 0) fused prep: cast x + transpose both weight matrices
    prep_fused<<<NCAST + NT1 + NT2, dim3(32, 8)>>>(x, xh, w_qkv, w1h, w_out, w2h);

    // 1) qkv (fp16) = x @ w_qkv, Q columns pre-scaled by 0.125*log2e
    gemm_h<1><<<dim3(D3 / 128, M / 128), 256, GSMEM_BYTES>>>(
        xh, w1h, nullptr, qh, M, D3, DMODEL, DMODEL);

    // 2) tensor-core causal flash attention -> fp16 att
    flash_mma<<<dim3(SLEN / 128, HEADS, BATCH), 256, FSMEM>>>(qh, ah);

    // 3) out = att @ w_out (fp32 out)
    gemm_h<0><<<dim3(DMODEL / 128, M / 128), 256, GSMEM_BYTES>>>(
        ah, w2h, out, nullptr, M, DMODEL, DMODEL, 0);
}